// round 8
// baseline (speedup 1.0000x reference)
#include <cuda_runtime.h>
#include <cstdint>

// ---------------------------------------------------------------------------
// SparseConv2D == dense VALID 3x3 conv (R3 derivation) * per-14x14-block
// active flag.  mma.sync m16n8k8 tf32 implicit GEMM.
// R7: B fragments pre-packed to GMEM (L1-resident via __ldg), smem holds only
// the x tile -> 16 warps/SM (was 12), bigger tile (16 rows), reg cap 128.
// ---------------------------------------------------------------------------

#define NIMG 8
#define HIN  506
#define WIN  506
#define CIN  32
#define OHW  504
#define NB   36

#define TROWS 16              // output rows per CTA (8 warps x 2 rows)
#define TCOLS 32              // output cols per CTA
#define XR    18              // input rows in tile
#define XC    34              // input cols in tile
#define PXF   36              // floats per pixel slot (144 B; /16 odd -> no conflicts)
#define SMEM_BYTES (XR * XC * PXF * 4)        // 88128 -> 2 CTAs/SM (176 KB)

#define THREADS 256
#define NCHUNK  32            // ceil(504/16)

__device__ float    d_active[NIMG * NB * NB];
__device__ uint32_t d_wpack[9 * 1024];        // [tap][lane][e] fragment order

// ------------------------------ helpers ------------------------------------
__device__ __forceinline__ uint32_t cvt_tf32(float f){
    uint32_t u; asm("cvt.rna.tf32.f32 %0, %1;" : "=r"(u) : "f"(f)); return u;
}
__device__ __forceinline__ void mma8(float* c,
                                     uint32_t a0, uint32_t a1, uint32_t a2, uint32_t a3,
                                     uint32_t b0, uint32_t b1){
    asm volatile(
        "mma.sync.aligned.m16n8k8.row.col.f32.tf32.tf32.f32 "
        "{%0,%1,%2,%3}, {%4,%5,%6,%7}, {%8,%9}, {%0,%1,%2,%3};"
        : "+f"(c[0]), "+f"(c[1]), "+f"(c[2]), "+f"(c[3])
        : "r"(a0), "r"(a1), "r"(a2), "r"(a3), "r"(b0), "r"(b1));
}

// ------------------- prepack weights into fragment order -------------------
// slot e of lane: nf=e>>3, s=(e>>1)&3, rg=e&1 holds
//   w[ci = t4*8 + 2*s + rg][cout = nf*8 + g],  g=lane>>2, t4=lane&3
__global__ void __launch_bounds__(256)
prepack_kernel(const float* __restrict__ kern){
    int idx = blockIdx.x * 256 + threadIdx.x;
    if (idx >= 9216) return;
    int t    = idx >> 10;
    int r    = idx & 1023;
    int lane = r >> 5;
    int e    = r & 31;
    int g  = lane >> 2, t4 = lane & 3;
    int nf = e >> 3,  s = (e >> 1) & 3, rg = e & 1;
    int ci = t4*8 + 2*s + rg;
    int co = nf*8 + g;
    d_wpack[idx] = cvt_tf32(kern[t*1024 + ci*32 + co]);
}

// ------------------------- active-flag kernel ------------------------------
__global__ void __launch_bounds__(256)
active_kernel(const float* __restrict__ mask){
    int w    = blockIdx.x * 8 + (threadIdx.x >> 5);
    int lane = threadIdx.x & 31;
    int n    = w / (NB*NB);
    int rem  = w - n * (NB*NB);
    int bi   = rem / NB;
    int bj   = rem - bi * NB;
    float m = -1e30f;
#pragma unroll
    for (int i = 0; i < 8; i++){
        int e = lane + 32*i, rr = e >> 4, cc = e & 15;
        m = fmaxf(m, mask[((size_t)n*HIN + bi*14 + rr)*WIN + (bj*14 + cc)]);
    }
#pragma unroll
    for (int off = 16; off; off >>= 1)
        m = fmaxf(m, __shfl_xor_sync(0xffffffffu, m, off));
    if (lane == 0) d_active[w] = (m > 0.5f) ? 1.0f : 0.0f;
}

// ----------------------------- conv kernel ---------------------------------
extern __shared__ char smem[];

__global__ void __launch_bounds__(THREADS, 2)
conv_mma(const float* __restrict__ x, const float* __restrict__ bias,
         float* __restrict__ out){
    const int tid  = threadIdx.x;
    const int wid  = tid >> 5;        // 0..7
    const int lane = tid & 31;
    const int g    = lane >> 2;
    const int t4   = lane & 3;

    const int c0 = blockIdx.x * TCOLS;         // 0..480
    const int R0 = blockIdx.y * TROWS;         // 0..496
    const int n  = blockIdx.z;

    uint32_t* xs = (uint32_t*)smem;

    // ---- stage x tile: 18x34 pixels, identity ci, pixel stride 36 floats.
    // __ldcs (streaming) keeps B-pack lines resident in L1.
    for (int e = tid; e < XR*XC; e += THREADS){
        int tr = e / XC, tc = e - tr*XC;
        int hh = R0 + tr, wc = c0 + tc;
        uint4* dst = (uint4*)(xs + e * PXF);
        if (hh < HIN && wc < WIN){
            const float4* src = (const float4*)(x + (((size_t)n*HIN + hh)*WIN + wc)*CIN);
#pragma unroll
            for (int j = 0; j < 8; j++){
                float4 v = __ldcs(src + j);
                dst[j] = make_uint4(cvt_tf32(v.x), cvt_tf32(v.y),
                                    cvt_tf32(v.z), cvt_tf32(v.w));
            }
        } else {
#pragma unroll
            for (int j = 0; j < 8; j++) dst[j] = make_uint4(0u,0u,0u,0u);
        }
    }
    __syncthreads();

    // ---- mainloop: warp = out rows R0+2*wid, +1; cols c0..c0+31 ----
    float acc[4][4][4];
#pragma unroll
    for (int f = 0; f < 4; f++)
#pragma unroll
        for (int nf = 0; nf < 4; nf++)
#pragma unroll
            for (int i = 0; i < 4; i++) acc[f][nf][i] = 0.0f;

    const int rowb = wid * 2;
    for (int dr = 0; dr < 3; dr++){
        for (int dc = 0; dc < 3; dc++){
            // B fragments: 8 x LDG.128 (L1-hit broadcast), reused by 4 m-frags
            uint32_t fb[32];
            const uint4* wt = (const uint4*)(d_wpack + (dr*3 + dc)*1024 + lane*32);
#pragma unroll
            for (int q = 0; q < 8; q++)
                *(uint4*)&fb[q*4] = __ldg(wt + q);

#pragma unroll
            for (int f = 0; f < 4; f++){
                const int trow = rowb + (f >> 1) + dr;
                const int coff = (f & 1) * 16 + dc;
                const char* pa = (const char*)xs + (trow*XC + coff) * (PXF*4) + t4*32;
                uint4 lo0 = *(const uint4*)(pa + g * (PXF*4));
                uint4 lo1 = *(const uint4*)(pa + g * (PXF*4) + 16);
                uint4 hi0 = *(const uint4*)(pa + (g+8) * (PXF*4));
                uint4 hi1 = *(const uint4*)(pa + (g+8) * (PXF*4) + 16);
                uint32_t alo[8] = {lo0.x, lo0.y, lo0.z, lo0.w,
                                   lo1.x, lo1.y, lo1.z, lo1.w};
                uint32_t ahi[8] = {hi0.x, hi0.y, hi0.z, hi0.w,
                                   hi1.x, hi1.y, hi1.z, hi1.w};
#pragma unroll
                for (int s = 0; s < 4; s++){
                    uint32_t a0 = alo[2*s],   a1 = ahi[2*s];
                    uint32_t a2 = alo[2*s+1], a3 = ahi[2*s+1];
#pragma unroll
                    for (int nf = 0; nf < 4; nf++)
                        mma8(acc[f][nf], a0, a1, a2, a3,
                             fb[nf*8 + s*2], fb[nf*8 + s*2 + 1]);
                }
            }
        }
    }

    // ---- epilogue: (+bias) * active, STG.64 ----
    const float* act = d_active + n * (NB*NB);
    float2 bv[4];
#pragma unroll
    for (int nf = 0; nf < 4; nf++)
        bv[nf] = *(const float2*)(bias + nf*8 + 2*t4);

#pragma unroll
    for (int f = 0; f < 4; f++){
        const int row = R0 + rowb + (f >> 1);
        if (row < OHW){
            const int rb = (row / 14) * NB;
            float* obase = out + (((size_t)n*OHW + row)*OHW) * CIN;
#pragma unroll
            for (int h = 0; h < 2; h++){
                int col = c0 + (f & 1)*16 + g + h*8;
                if (col < OHW){
                    float fa = act[rb + col/14];
                    float* op = obase + (size_t)col * CIN + 2*t4;
#pragma unroll
                    for (int nf = 0; nf < 4; nf++){
                        float2 v;
                        v.x = (acc[f][nf][h*2 + 0] + bv[nf].x) * fa;
                        v.y = (acc[f][nf][h*2 + 1] + bv[nf].y) * fa;
                        *(float2*)(op + nf*8) = v;
                    }
                }
            }
        }
    }
}

// ------------------------------- launch ------------------------------------
extern "C" void kernel_launch(void* const* d_in, const int* in_sizes, int n_in,
                              void* d_out, int out_size){
    const float* x    = (const float*)d_in[0];
    const float* mask = (const float*)d_in[1];
    const float* kern = (const float*)d_in[2];
    const float* bias = (const float*)d_in[3];
    float* out = (float*)d_out;

    prepack_kernel<<<36, 256>>>(kern);
    active_kernel<<<1296, 256>>>(mask);

    cudaFuncSetAttribute(conv_mma, cudaFuncAttributeMaxDynamicSharedMemorySize,
                         SMEM_BYTES);
    dim3 grid(16, NCHUNK, NIMG);   // col bands x row chunks x images
    conv_mma<<<grid, THREADS, SMEM_BYTES>>>(x, bias, out);
}

// round 9
// speedup vs baseline: 2.2561x; 2.2561x over previous
#include <cuda_runtime.h>
#include <cuda_fp16.h>
#include <cstdint>

// ---------------------------------------------------------------------------
// SparseConv2D == dense VALID 3x3 conv (R3 derivation) * per-14x14-block
// active flag.  R8: mma.sync m16n8k16 FP16 implicit GEMM (f32 accumulate).
// fp16 mantissa == tf32 mantissa (10 bits), so accuracy matches R6 (~3e-4).
// Halves tensor-instr count AND smem crossbar traffic vs tf32 path.
// ---------------------------------------------------------------------------

#define NIMG 8
#define HIN  506
#define WIN  506
#define CIN  32
#define OHW  504
#define NB   36

#define TROWS 16              // output rows per CTA (8 warps x 2 rows)
#define TCOLS 32              // output cols per CTA
#define XR    18              // input rows in tile
#define XC    34              // input cols in tile
#define PXB   96              // bytes per pixel slot (64B data + pad; 96 mod 128
                              // pattern -> conflict-free LDS.64 reads)
#define XS_BYTES (XR * XC * PXB)              // 58752
#define W_OFF    XS_BYTES
#define SMEM_BYTES (W_OFF + 9 * 2048)         // 77184 -> 2 CTAs/SM (154 KB)

#define THREADS 256
#define NCHUNK  32            // ceil(504/16)

__device__ float d_active[NIMG * NB * NB];

// ------------------------------ helpers ------------------------------------
__device__ __forceinline__ uint32_t packh2(float lo, float hi){
    __half2 h = __floats2half2_rn(lo, hi);    // .x = lo half
    return *(uint32_t*)&h;
}
__device__ __forceinline__ void mma16(float* c,
                                      uint32_t a0, uint32_t a1, uint32_t a2, uint32_t a3,
                                      uint32_t b0, uint32_t b1){
    asm volatile(
        "mma.sync.aligned.m16n8k16.row.col.f32.f16.f16.f32 "
        "{%0,%1,%2,%3}, {%4,%5,%6,%7}, {%8,%9}, {%0,%1,%2,%3};"
        : "+f"(c[0]), "+f"(c[1]), "+f"(c[2]), "+f"(c[3])
        : "r"(a0), "r"(a1), "r"(a2), "r"(a3), "r"(b0), "r"(b1));
}

// ------------------------- active-flag kernel ------------------------------
__global__ void __launch_bounds__(256)
active_kernel(const float* __restrict__ mask){
    int w    = blockIdx.x * 8 + (threadIdx.x >> 5);
    int lane = threadIdx.x & 31;
    int n    = w / (NB*NB);
    int rem  = w - n * (NB*NB);
    int bi   = rem / NB;
    int bj   = rem - bi * NB;
    float m = -1e30f;
#pragma unroll
    for (int i = 0; i < 8; i++){
        int e = lane + 32*i, rr = e >> 4, cc = e & 15;
        m = fmaxf(m, mask[((size_t)n*HIN + bi*14 + rr)*WIN + (bj*14 + cc)]);
    }
#pragma unroll
    for (int off = 16; off; off >>= 1)
        m = fmaxf(m, __shfl_xor_sync(0xffffffffu, m, off));
    if (lane == 0) d_active[w] = (m > 0.5f) ? 1.0f : 0.0f;
}

// ----------------------------- conv kernel ---------------------------------
extern __shared__ char smem[];

__global__ void __launch_bounds__(THREADS, 2)
conv_mma(const float* __restrict__ x, const float* __restrict__ kern,
         const float* __restrict__ bias, float* __restrict__ out){
    const int tid  = threadIdx.x;
    const int wid  = tid >> 5;        // 0..7
    const int lane = tid & 31;
    const int g    = lane >> 2;       // groupID
    const int t4   = lane & 3;        // threadID_in_group

    const int c0 = blockIdx.x * TCOLS;         // 0..480
    const int R0 = blockIdx.y * TROWS;         // 0..496
    const int n  = blockIdx.z;

    char* xs = smem;
    char* ws = smem + W_OFF;

    // ---- stage weights, per-lane fragment order (64B/lane/tap), fp16.
    // slot q (16B, XOR-swizzled by (lane>>1)&3): ks=q>>1, nfp=q&1; words:
    //   [b0(nf=2nfp), b1(2nfp), b0(2nfp+1), b1(2nfp+1)]
    //   b0 = (k=ks*16+2t4, +1), b1 = (k=ks*16+8+2t4, +1), n = nf*8+g
    for (int t = wid; t < 9; t += 8){
        const float* kt = kern + t * 1024;     // [ci][co], ci stride 32
        char* base = ws + t * 2048 + lane * 64;
#pragma unroll
        for (int q = 0; q < 4; q++){
            int ks = q >> 1, nfp = q & 1;
            int kb = ks*16 + 2*t4;
            uint4 u;
            {
                int co = (2*nfp)*8 + g;
                u.x = packh2(kt[kb*32 + co],     kt[(kb+1)*32 + co]);
                u.y = packh2(kt[(kb+8)*32 + co], kt[(kb+9)*32 + co]);
            }
            {
                int co = (2*nfp+1)*8 + g;
                u.z = packh2(kt[kb*32 + co],     kt[(kb+1)*32 + co]);
                u.w = packh2(kt[(kb+8)*32 + co], kt[(kb+9)*32 + co]);
            }
            *(uint4*)(base + ((q ^ ((lane>>1)&3)) * 16)) = u;
        }
    }

    // ---- stage x tile: 18x34 pixels, fp16, interleaved ci order so lane
    // LDS.64 at t4*8 (+ks*32) returns (a0,a2) pairs:
    //   bytes [0..31]=ks0: ci [0,1,8,9, 2,3,10,11, 4,5,12,13, 6,7,14,15]
    //   bytes [32..63]=ks1: same +16
    for (int e = tid; e < XR*XC; e += THREADS){
        int tr = e / XC, tc = e - tr*XC;
        int hh = R0 + tr, wc = c0 + tc;
        uint32_t wb[16];
        if (hh < HIN && wc < WIN){
            const float4* src = (const float4*)(x + (((size_t)n*HIN + hh)*WIN + wc)*CIN);
#pragma unroll
            for (int j = 0; j < 8; j++){
                float4 v = src[j];
                int ks = j >> 2;
                int rr = (4*j) & 15;             // 0,4,8,12
                int w1, w2;
                if (rr < 8){ w1 = ks*8 + (rr>>1)*2;       w2 = ks*8 + ((rr+2)>>1)*2; }
                else       { w1 = ks*8 + ((rr-8)>>1)*2+1; w2 = ks*8 + ((rr-6)>>1)*2+1; }
                wb[w1] = packh2(v.x, v.y);
                wb[w2] = packh2(v.z, v.w);
            }
        } else {
#pragma unroll
            for (int j = 0; j < 16; j++) wb[j] = 0u;
        }
        uint4* dst = (uint4*)(xs + e * PXB);
#pragma unroll
        for (int q = 0; q < 4; q++)
            dst[q] = make_uint4(wb[q*4], wb[q*4+1], wb[q*4+2], wb[q*4+3]);
    }
    __syncthreads();

    // ---- mainloop: warp = out rows R0+2*wid, +1; cols c0..c0+31 ----
    float acc[4][4][4];
#pragma unroll
    for (int f = 0; f < 4; f++)
#pragma unroll
        for (int nf = 0; nf < 4; nf++)
#pragma unroll
            for (int i = 0; i < 4; i++) acc[f][nf][i] = 0.0f;

    const int rowb = wid * 2;
    for (int dr = 0; dr < 3; dr++){
        for (int dc = 0; dc < 3; dc++){
            // B fragments: 4 LDS.128, conflict-free, reused by 4 m-frags
            uint32_t fb[16];
            const char* wt = ws + (dr*3 + dc) * 2048 + lane * 64;
#pragma unroll
            for (int q = 0; q < 4; q++)
                *(uint4*)&fb[q*4] = *(const uint4*)(wt + ((q ^ ((lane>>1)&3)) * 16));

#pragma unroll
            for (int f = 0; f < 4; f++){
                const int trow = rowb + (f >> 1) + dr;
                const int coff = (f & 1) * 16 + dc;
                const char* pb = xs + (trow*XC + coff) * PXB + t4*8;
#pragma unroll
                for (int ks = 0; ks < 2; ks++){
                    uint2 lo = *(const uint2*)(pb + g*PXB     + ks*32);
                    uint2 hi = *(const uint2*)(pb + (g+8)*PXB + ks*32);
                    // a0=lo.x (row g,k 2t4..), a2=lo.y (k 8+2t4..), a1/a3 from g+8
#pragma unroll
                    for (int nf = 0; nf < 4; nf++){
                        int qb = (ks*2 + (nf>>1))*4 + (nf&1)*2;
                        mma16(acc[f][nf], lo.x, hi.x, lo.y, hi.y,
                              fb[qb], fb[qb+1]);
                    }
                }
            }
        }
    }

    // ---- epilogue: (+bias) * active, STG.64 ----
    const float* act = d_active + n * (NB*NB);
    float2 bv[4];
#pragma unroll
    for (int nf = 0; nf < 4; nf++)
        bv[nf] = *(const float2*)(bias + nf*8 + 2*t4);

#pragma unroll
    for (int f = 0; f < 4; f++){
        const int row = R0 + rowb + (f >> 1);
        if (row < OHW){
            const int rb = (row / 14) * NB;
            float* obase = out + (((size_t)n*OHW + row)*OHW) * CIN;
#pragma unroll
            for (int h = 0; h < 2; h++){
                int col = c0 + (f & 1)*16 + g + h*8;
                if (col < OHW){
                    float fa = act[rb + col/14];
                    float* op = obase + (size_t)col * CIN + 2*t4;
#pragma unroll
                    for (int nf = 0; nf < 4; nf++){
                        float2 v;
                        v.x = (acc[f][nf][h*2 + 0] + bv[nf].x) * fa;
                        v.y = (acc[f][nf][h*2 + 1] + bv[nf].y) * fa;
                        *(float2*)(op + nf*8) = v;
                    }
                }
            }
        }
    }
}

// ------------------------------- launch ------------------------------------
extern "C" void kernel_launch(void* const* d_in, const int* in_sizes, int n_in,
                              void* d_out, int out_size){
    const float* x    = (const float*)d_in[0];
    const float* mask = (const float*)d_in[1];
    const float* kern = (const float*)d_in[2];
    const float* bias = (const float*)d_in[3];
    float* out = (float*)d_out;

    active_kernel<<<1296, 256>>>(mask);

    cudaFuncSetAttribute(conv_mma, cudaFuncAttributeMaxDynamicSharedMemorySize,
                         SMEM_BYTES);
    dim3 grid(16, NCHUNK, NIMG);   // col bands x row chunks x images
    conv_mma<<<grid, THREADS, SMEM_BYTES>>>(x, kern, bias, out);
}

// round 10
// speedup vs baseline: 2.3318x; 1.0336x over previous
#include <cuda_runtime.h>
#include <cuda_fp16.h>
#include <cstdint>

// ---------------------------------------------------------------------------
// SparseConv2D == dense VALID 3x3 conv (R3 derivation) * per-14x14-block
// active flag.  mma.sync m16n8k16 FP16 implicit GEMM (f32 accumulate).
// R9: A fragments via ldmatrix.x4 (conflict-free, pixel stride 80B), fixing
// the 2-way LDS.64 bank conflicts of R8.  B path unchanged.
// ---------------------------------------------------------------------------

#define NIMG 8
#define HIN  506
#define WIN  506
#define CIN  32
#define OHW  504
#define NB   36

#define TROWS 16              // output rows per CTA (8 warps x 2 rows)
#define TCOLS 32              // output cols per CTA
#define XR    18              // input rows in tile
#define XC    34              // input cols in tile
#define PXB   80              // bytes per pixel (64B fp16 data + 16B pad);
                              // i*80 mod 128 all-distinct -> conflict-free
#define XS_BYTES (XR * XC * PXB)              // 48960
#define W_OFF    XS_BYTES
#define SMEM_BYTES (W_OFF + 9 * 2048)         // 67392 -> 2 CTAs/SM (135 KB)

#define THREADS 256
#define NCHUNK  32            // 504/16 = 31.5 -> 32

__device__ float d_active[NIMG * NB * NB];

// ------------------------------ helpers ------------------------------------
__device__ __forceinline__ uint32_t s2u(const void* p){
    uint32_t a;
    asm("{ .reg .u64 t; cvta.to.shared.u64 t, %1; cvt.u32.u64 %0, t; }"
        : "=r"(a) : "l"(p));
    return a;
}
__device__ __forceinline__ uint32_t packh2(float lo, float hi){
    __half2 h = __floats2half2_rn(lo, hi);    // .x = lo half
    return *(uint32_t*)&h;
}
__device__ __forceinline__ void ldmA(uint32_t& a0, uint32_t& a1,
                                     uint32_t& a2, uint32_t& a3, uint32_t saddr){
    asm volatile("ldmatrix.sync.aligned.m8n8.x4.shared.b16 {%0,%1,%2,%3}, [%4];"
                 : "=r"(a0), "=r"(a1), "=r"(a2), "=r"(a3) : "r"(saddr));
}
__device__ __forceinline__ void mma16(float* c,
                                      uint32_t a0, uint32_t a1, uint32_t a2, uint32_t a3,
                                      uint32_t b0, uint32_t b1){
    asm volatile(
        "mma.sync.aligned.m16n8k16.row.col.f32.f16.f16.f32 "
        "{%0,%1,%2,%3}, {%4,%5,%6,%7}, {%8,%9}, {%0,%1,%2,%3};"
        : "+f"(c[0]), "+f"(c[1]), "+f"(c[2]), "+f"(c[3])
        : "r"(a0), "r"(a1), "r"(a2), "r"(a3), "r"(b0), "r"(b1));
}

// ------------------------- active-flag kernel ------------------------------
__global__ void __launch_bounds__(256)
active_kernel(const float* __restrict__ mask){
    int w    = blockIdx.x * 8 + (threadIdx.x >> 5);
    int lane = threadIdx.x & 31;
    int n    = w / (NB*NB);
    int rem  = w - n * (NB*NB);
    int bi   = rem / NB;
    int bj   = rem - bi * NB;
    float m = -1e30f;
#pragma unroll
    for (int i = 0; i < 8; i++){
        int e = lane + 32*i, rr = e >> 4, cc = e & 15;
        m = fmaxf(m, mask[((size_t)n*HIN + bi*14 + rr)*WIN + (bj*14 + cc)]);
    }
#pragma unroll
    for (int off = 16; off; off >>= 1)
        m = fmaxf(m, __shfl_xor_sync(0xffffffffu, m, off));
    if (lane == 0) d_active[w] = (m > 0.5f) ? 1.0f : 0.0f;
}

// ----------------------------- conv kernel ---------------------------------
extern __shared__ char smem[];

__global__ void __launch_bounds__(THREADS, 2)
conv_mma(const float* __restrict__ x, const float* __restrict__ kern,
         const float* __restrict__ bias, float* __restrict__ out){
    const int tid  = threadIdx.x;
    const int wid  = tid >> 5;        // 0..7
    const int lane = tid & 31;
    const int g    = lane >> 2;
    const int t4   = lane & 3;

    const int c0 = blockIdx.x * TCOLS;         // 0..480
    const int R0 = blockIdx.y * TROWS;         // 0..496
    const int n  = blockIdx.z;

    char* xs = smem;
    char* ws = smem + W_OFF;
    const uint32_t xs_u = s2u(xs);

    // ---- stage weights, per-lane fragment order (64B/lane/tap), fp16.
    // slot q (16B, swizzle q^((lane>>1)&3)): ks=q>>1, nfp=q&1; words:
    //   [b0(nf=2nfp), b1(2nfp), b0(2nfp+1), b1(2nfp+1)]
    //   b0 = (k=ks*16+2t4, +1), b1 = (k=ks*16+8+2t4, +1), n = nf*8+g
    for (int t = wid; t < 9; t += 8){
        const float* kt = kern + t * 1024;     // [ci][co], ci stride 32
        char* base = ws + t * 2048 + lane * 64;
#pragma unroll
        for (int q = 0; q < 4; q++){
            int ks = q >> 1, nfp = q & 1;
            int kb = ks*16 + 2*t4;
            uint4 u;
            {
                int co = (2*nfp)*8 + g;
                u.x = packh2(kt[kb*32 + co],     kt[(kb+1)*32 + co]);
                u.y = packh2(kt[(kb+8)*32 + co], kt[(kb+9)*32 + co]);
            }
            {
                int co = (2*nfp+1)*8 + g;
                u.z = packh2(kt[kb*32 + co],     kt[(kb+1)*32 + co]);
                u.w = packh2(kt[(kb+8)*32 + co], kt[(kb+9)*32 + co]);
            }
            *(uint4*)(base + ((q ^ ((lane>>1)&3)) * 16)) = u;
        }
    }

    // ---- stage x tile: 18x34 pixels, fp16 natural ci order, stride 80B.
    // STS.128: 8 consecutive lanes hit distinct 16B banks (delta 80B) -> clean.
    for (int e = tid; e < XR*XC; e += THREADS){
        int tr = e / XC, tc = e - tr*XC;
        int hh = R0 + tr, wc = c0 + tc;
        uint4* dst = (uint4*)(xs + e * PXB);
        if (hh < HIN && wc < WIN){
            const float4* src = (const float4*)(x + (((size_t)n*HIN + hh)*WIN + wc)*CIN);
#pragma unroll
            for (int q = 0; q < 4; q++){
                float4 v0 = src[q*2], v1 = src[q*2+1];
                dst[q] = make_uint4(packh2(v0.x, v0.y), packh2(v0.z, v0.w),
                                    packh2(v1.x, v1.y), packh2(v1.z, v1.w));
            }
        } else {
#pragma unroll
            for (int q = 0; q < 4; q++) dst[q] = make_uint4(0u,0u,0u,0u);
        }
    }
    __syncthreads();

    // ---- mainloop: warp = out rows R0+2*wid, +1; cols c0..c0+31 ----
    float acc[4][4][4];
#pragma unroll
    for (int f = 0; f < 4; f++)
#pragma unroll
        for (int nf = 0; nf < 4; nf++)
#pragma unroll
            for (int i = 0; i < 4; i++) acc[f][nf][i] = 0.0f;

    const int rowb = wid * 2;
    // ldmatrix per-lane offset: lanes 0-15 -> pixel rows 0-15 (k low 16B),
    // lanes 16-31 -> same rows, +16B (k cols 8-15)
    const uint32_t laneoff = (uint32_t)((lane & 15) * PXB + (lane >> 4) * 16);

    for (int dr = 0; dr < 3; dr++){
        for (int dc = 0; dc < 3; dc++){
            // B fragments: 4 LDS.128, conflict-free, reused by 4 m-frags
            uint32_t fb[16];
            const char* wt = ws + (dr*3 + dc) * 2048 + lane * 64;
#pragma unroll
            for (int q = 0; q < 4; q++)
                *(uint4*)&fb[q*4] = *(const uint4*)(wt + ((q ^ ((lane>>1)&3)) * 16));

#pragma unroll
            for (int f = 0; f < 4; f++){
                const int trow = rowb + (f >> 1) + dr;
                const int coff = (f & 1) * 16 + dc;
                const uint32_t abase = xs_u + (uint32_t)((trow*XC + coff) * PXB) + laneoff;
#pragma unroll
                for (int ks = 0; ks < 2; ks++){
                    uint32_t a0, a1, a2, a3;
                    ldmA(a0, a1, a2, a3, abase + ks*32);
#pragma unroll
                    for (int nf = 0; nf < 4; nf++){
                        int qb = (ks*2 + (nf>>1))*4 + (nf&1)*2;
                        mma16(acc[f][nf], a0, a1, a2, a3, fb[qb], fb[qb+1]);
                    }
                }
            }
        }
    }

    // ---- epilogue: (+bias) * active, STG.64 ----
    const float* act = d_active + n * (NB*NB);
    float2 bv[4];
#pragma unroll
    for (int nf = 0; nf < 4; nf++)
        bv[nf] = *(const float2*)(bias + nf*8 + 2*t4);

#pragma unroll
    for (int f = 0; f < 4; f++){
        const int row = R0 + rowb + (f >> 1);
        if (row < OHW){
            const int rb = (row / 14) * NB;
            float* obase = out + (((size_t)n*OHW + row)*OHW) * CIN;
#pragma unroll
            for (int h = 0; h < 2; h++){
                int col = c0 + (f & 1)*16 + g + h*8;
                if (col < OHW){
                    float fa = act[rb + col/14];
                    float* op = obase + (size_t)col * CIN + 2*t4;
#pragma unroll
                    for (int nf = 0; nf < 4; nf++){
                        float2 v;
                        v.x = (acc[f][nf][h*2 + 0] + bv[nf].x) * fa;
                        v.y = (acc[f][nf][h*2 + 1] + bv[nf].y) * fa;
                        *(float2*)(op + nf*8) = v;
                    }
                }
            }
        }
    }
}

// ------------------------------- launch ------------------------------------
extern "C" void kernel_launch(void* const* d_in, const int* in_sizes, int n_in,
                              void* d_out, int out_size){
    const float* x    = (const float*)d_in[0];
    const float* mask = (const float*)d_in[1];
    const float* kern = (const float*)d_in[2];
    const float* bias = (const float*)d_in[3];
    float* out = (float*)d_out;

    active_kernel<<<1296, 256>>>(mask);

    cudaFuncSetAttribute(conv_mma, cudaFuncAttributeMaxDynamicSharedMemorySize,
                         SMEM_BYTES);
    dim3 grid(16, NCHUNK, NIMG);   // col bands x row chunks x images
    conv_mma<<<grid, THREADS, SMEM_BYTES>>>(x, kern, bias, out);
}